// round 2
// baseline (speedup 1.0000x reference)
#include <cuda_runtime.h>
#include <math.h>

// Hawkes univariate NLL.
// x sorted per row => excitation sum factorizes into a prefix scan:
//   S[j] = exp(-w x_j) * sum_{i<j} exp(w x_i)  -  (# earlier duplicates of x_j)
// Kernel A: one block per batch row, 3-level scan + elementwise + block reduce.
// Kernel B: combine partials into the scalar loss.

#define HK_N       8192
#define HK_THREADS 1024
#define HK_VPT     (HK_N / HK_THREADS)   // 8 values per thread
#define HK_T       1.0f
#define HK_REG     0.01f

__device__ float g_hk_partial[64];

__global__ __launch_bounds__(HK_THREADS)
void hawkes_row_kernel(const float* __restrict__ x,
                       const float* __restrict__ mu_p,
                       const float* __restrict__ alpha_p,
                       const float* __restrict__ w_p) {
    __shared__ float xs[HK_N];
    __shared__ float warp_scan[32];
    __shared__ float red[32];

    const int b   = blockIdx.x;
    const int tid = threadIdx.x;
    const float* __restrict__ xr = x + (size_t)b * HK_N;

    const float mu    = *mu_p;
    const float alpha = *alpha_p;
    const float w     = *w_p;

    // Load row into shared memory (coalesced).
    #pragma unroll
    for (int i = tid; i < HK_N; i += HK_THREADS) xs[i] = xr[i];
    __syncthreads();

    // ---- Level 1: per-thread sequential inclusive scan of exp(w*x) ----
    const int base = tid * HK_VPT;
    float e[HK_VPT], s[HK_VPT];
    float run = 0.0f;
    #pragma unroll
    for (int k = 0; k < HK_VPT; k++) {
        float xi = xs[base + k];
        e[k] = __expf(w * xi);
        run += e[k];
        s[k] = run;                 // inclusive within thread
    }

    // ---- Level 2: warp inclusive scan of thread totals ----
    const unsigned lane = tid & 31u;
    const unsigned wid  = tid >> 5;
    float v = run;
    #pragma unroll
    for (int off = 1; off < 32; off <<= 1) {
        float n = __shfl_up_sync(0xffffffffu, v, off);
        if (lane >= (unsigned)off) v += n;
    }
    if (lane == 31u) warp_scan[wid] = v;
    __syncthreads();

    // ---- Level 3: scan of the 32 warp sums (warp 0) ----
    if (wid == 0) {
        float wv = (lane < (HK_THREADS / 32)) ? warp_scan[lane] : 0.0f;
        #pragma unroll
        for (int off = 1; off < 32; off <<= 1) {
            float n = __shfl_up_sync(0xffffffffu, wv, off);
            if (lane >= (unsigned)off) wv += n;
        }
        warp_scan[lane] = wv;       // inclusive scan of warp sums
    }
    __syncthreads();

    // Exclusive prefix of this thread's total across the whole block.
    const float thread_excl = (v - run) + ((wid > 0) ? warp_scan[wid - 1] : 0.0f);

    // ---- Elementwise: excite, pos, neg; accumulate (neg - pos) ----
    float acc = 0.0f;
    #pragma unroll
    for (int k = 0; k < HK_VPT; k++) {
        const int j = base + k;
        const float xj = xs[j];
        // exclusive prefix sum of exp(w*x_i) over i < j
        const float P = thread_excl + s[k] - e[k];

        // duplicate-timestamp correction: earlier equal x contribute exactly 1
        // to exp(-w xj)*P but are masked (delta<=0) in the reference.
        float c = 0.0f;
        int p = j - 1;
        while (p >= 0 && xs[p] == xj) { c += 1.0f; --p; }

        float S = __expf(-w * xj) * P - c;
        if (S < 0.0f) S = 0.0f;     // guard fp round-off for tiny prefixes

        const float excite = alpha * w * S;
        const float pos = __logf(mu + excite);
        const float neg = alpha * (1.0f - __expf(-w * (HK_T - xj)));
        acc += neg - pos;
    }

    // ---- Block reduction of acc ----
    #pragma unroll
    for (int off = 16; off > 0; off >>= 1)
        acc += __shfl_down_sync(0xffffffffu, acc, off);
    if (lane == 0u) red[wid] = acc;
    __syncthreads();
    if (wid == 0) {
        float r = (lane < (HK_THREADS / 32)) ? red[lane] : 0.0f;
        #pragma unroll
        for (int off = 16; off > 0; off >>= 1)
            r += __shfl_down_sync(0xffffffffu, r, off);
        if (lane == 0u) g_hk_partial[b] = r;
    }
}

__global__ void hawkes_final_kernel(const float* __restrict__ mu_p,
                                    const float* __restrict__ alpha_p,
                                    const float* __restrict__ w_p,
                                    float* __restrict__ out, int B) {
    const float mu    = *mu_p;
    const float alpha = *alpha_p;
    const float w     = *w_p;
    float sum = 0.0f;
    for (int b = 0; b < B; b++) sum += g_hk_partial[b];
    out[0] = mu * HK_T + sum
           + HK_REG * (-__logf(mu) - __logf(alpha) - __logf(w));
}

extern "C" void kernel_launch(void* const* d_in, const int* in_sizes, int n_in,
                              void* d_out, int out_size) {
    const float* x     = (const float*)d_in[0];
    const float* mu    = (const float*)d_in[1];
    const float* alpha = (const float*)d_in[2];
    const float* w     = (const float*)d_in[3];
    float* out = (float*)d_out;

    const int total = in_sizes[0];
    const int B = total / HK_N;     // shapes fixed: B=2, N=8192

    hawkes_row_kernel<<<B, HK_THREADS>>>(x, mu, alpha, w);
    hawkes_final_kernel<<<1, 1>>>(mu, alpha, w, out, B);
}